// round 12
// baseline (speedup 1.0000x reference)
#include <cuda_runtime.h>

#define NN   50000
#define EE   800000
#define TE   (EE + NN)
#define CIN  128
#define COUT 64

#define SCAN_B   512
#define SCAN_G   ((NN + SCAN_B - 1) / SCAN_B)   // 98

typedef unsigned long long u64;

#define FMA_F32X2(d, a, b, c) \
    asm("fma.rn.f32x2 %0, %1, %2, %3;" : "=l"(d) : "l"(a), "l"(b), "l"(c))

// ---- device scratch (16B-aligned for float4 access) ----
__device__ __align__(16) float g_xl[NN * COUT];     // x @ W_l
__device__ __align__(16) float g_xr[NN * COUT];     // x @ W_r
__device__ __align__(16) int   g_cnt[NN];           // per-dst degree
__device__ __align__(16) int   g_rowptr[NN + 1];    // CSR row pointers
__device__ __align__(16) int   g_cursor[NN];        // fill cursors
__device__ __align__(16) int   g_srcs[TE];          // CSR: src per slot
__device__ __align__(16) int   g_bsum[SCAN_G];      // per-block totals
__device__ __align__(16) int   g_boff[SCAN_G];      // per-block offsets

__device__ __forceinline__ int clampN(int v) {
    return v < 0 ? 0 : (v >= NN ? NN - 1 : v);
}

// ---------------------------------------------------------------- K0: init
__global__ void k_init() {
    int i = blockIdx.x * blockDim.x + threadIdx.x;
    if (i < NN) g_cnt[i] = 0;
}

// ----------------------------------------------------- K1: count edges/dst
__global__ void k_count(const int* __restrict__ ei) {
    int e = blockIdx.x * blockDim.x + threadIdx.x;
    if (e >= TE) return;
    int d = (e < EE) ? clampN(ei[EE + e]) : (e - EE);
    atomicAdd(&g_cnt[d], 1);
}

// ------------------- K2a: block-local exclusive scan + block totals
__global__ void k_scanA() {
    __shared__ int warp_sums[16];
    int tid = threadIdx.x, lane = tid & 31, wid = tid >> 5;
    int i = blockIdx.x * SCAN_B + tid;

    int v = (i < NN) ? g_cnt[i] : 0;
    int x = v;
    #pragma unroll
    for (int off = 1; off < 32; off <<= 1) {
        int y = __shfl_up_sync(0xffffffffu, x, off);
        if (lane >= off) x += y;
    }
    if (lane == 31) warp_sums[wid] = x;
    __syncthreads();
    if (wid == 0 && lane < 16) {
        int w = warp_sums[lane];
        #pragma unroll
        for (int off = 1; off < 16; off <<= 1) {
            int y = __shfl_up_sync(0x0000ffffu, w, off);
            if (lane >= off) w += y;
        }
        warp_sums[lane] = w;
    }
    __syncthreads();
    int warp_off = (wid > 0) ? warp_sums[wid - 1] : 0;
    if (i < NN) g_rowptr[i] = warp_off + x - v;
    if (tid == 0) g_bsum[blockIdx.x] = warp_sums[15];
}

// ------------------- K2b: exclusive scan of 98 block totals
__global__ void k_scanB() {
    __shared__ int s[128];
    int t = threadIdx.x;
    s[t] = (t < SCAN_G) ? g_bsum[t] : 0;
    __syncthreads();
    #pragma unroll
    for (int off = 1; off < 128; off <<= 1) {
        int v = (t >= off) ? s[t - off] : 0;
        __syncthreads();
        s[t] += v;
        __syncthreads();
    }
    if (t < SCAN_G) g_boff[t] = s[t] - g_bsum[t];
    if (t == 0) g_rowptr[NN] = TE;
}

// ------------------- K2c: apply block offsets, materialize cursors
__global__ void k_scanC() {
    int i = blockIdx.x * SCAN_B + threadIdx.x;
    if (i >= NN) return;
    int r = g_rowptr[i] + g_boff[blockIdx.x];
    g_rowptr[i] = r;
    g_cursor[i] = r;
}

// ------------------------------------------- K3: x@[W_l|W_r] fused GEMM
// f32x2 packed FFMA, pairing across k. Ws layout: [(k/2)][c][k&1].
__global__ void __launch_bounds__(256) k_gemm(const float* __restrict__ x,
                                              const float* __restrict__ Wl,
                                              const float* __restrict__ Wr) {
    __shared__ float Ws[64 * 128];   // 32KB, paired-k layout
    __shared__ float xs[64 * 64];    // 16KB, row-major (k contiguous)

    const int tid  = threadIdx.x;
    const int base = blockIdx.x * 64;
    const int tx = tid & 31, ty = tid >> 5;

    u64 acc2[8][4];
    #pragma unroll
    for (int i = 0; i < 8; i++)
        #pragma unroll
        for (int j = 0; j < 4; j++) acc2[i][j] = 0ull;

    for (int kc = 0; kc < 2; kc++) {
        const int k0 = kc * 64;
        // W chunk -> paired-k layout: Ws[(kk>>1)*256 + c*2 + (kk&1)]
        for (int idx = tid * 4; idx < 64 * 128; idx += 256 * 4) {
            int kk = idx >> 7, c = idx & 127;
            int k = k0 + kk;
            const float* p = (c < 64) ? (Wl + k * 64 + c)
                                      : (Wr + k * 64 + (c - 64));
            float4 v = *(const float4*)p;
            float* dst = &Ws[(kk >> 1) * 256 + (kk & 1)];
            dst[(c + 0) * 2] = v.x;
            dst[(c + 1) * 2] = v.y;
            dst[(c + 2) * 2] = v.z;
            dst[(c + 3) * 2] = v.w;
        }
        // x tile chunk (natural layout: consecutive k adjacent)
        for (int idx = tid * 4; idx < 64 * 64; idx += 256 * 4) {
            int r = idx >> 6;
            int row = base + r;
            float4 v = make_float4(0.f, 0.f, 0.f, 0.f);
            if (row < NN) v = *(const float4*)&x[row * CIN + k0 + (idx & 63)];
            *(float4*)&xs[idx] = v;
        }
        __syncthreads();

        #pragma unroll 4
        for (int kp = 0; kp < 32; kp++) {
            u64 wv2[4];
            #pragma unroll
            for (int j = 0; j < 4; j++)
                wv2[j] = *(const u64*)&Ws[kp * 256 + (tx + 32 * j) * 2];
            #pragma unroll
            for (int i = 0; i < 8; i++) {
                u64 xv2 = *(const u64*)&xs[(ty + 8 * i) * 64 + kp * 2];
                #pragma unroll
                for (int j = 0; j < 4; j++)
                    FMA_F32X2(acc2[i][j], xv2, wv2[j], acc2[i][j]);
            }
        }
        __syncthreads();
    }

    #pragma unroll
    for (int i = 0; i < 8; i++) {
        int row = base + ty + 8 * i;
        if (row >= NN) continue;
        #pragma unroll
        for (int j = 0; j < 4; j++) {
            float lo = __uint_as_float((unsigned)(acc2[i][j] & 0xffffffffull));
            float hi = __uint_as_float((unsigned)(acc2[i][j] >> 32));
            float a = lo + hi;
            int c = tx + 32 * j;
            if (c < 64) g_xl[row * 64 + c]        = a;
            else        g_xr[row * 64 + (c - 64)] = a;
        }
    }
}

// --------------------- K4: CSR src fill only (no math)
__global__ void k_fill(const int* __restrict__ ei) {
    int e = blockIdx.x * blockDim.x + threadIdx.x;
    if (e >= TE) return;
    int s, d;
    if (e < EE) { s = clampN(ei[e]); d = clampN(ei[EE + e]); }
    else        { s = d = e - EE; }
    int pos = atomicAdd(&g_cursor[d], 1);
    g_srcs[pos] = s;
}

// -------- K5: fused online-softmax aggregation + epilogue (warp per node)
// Round-7 version: single edge per iter, software prefetch, warp-uniform
// branch with 1-MUFU common path.
__global__ void k_aggr(float* __restrict__ out,
                       const float* __restrict__ att,
                       const float* __restrict__ bias) {
    int node = (blockIdx.x * blockDim.x + threadIdx.x) >> 5;
    int lane = threadIdx.x & 31;

    int beg = g_rowptr[node], end = g_rowptr[node + 1];

    float att0 = att[lane],  att1 = att[lane + 32];
    float xr0  = g_xr[node * 64 + lane];
    float xr1  = g_xr[node * 64 + 32 + lane];

    float m = -3.4e38f, denom = 0.f, acc0 = 0.f, acc1 = 0.f;

    // prefetch first edge (degree >= 1 guaranteed by self loops)
    int s = g_srcs[beg];
    float x0 = g_xl[s * 64 + lane];
    float x1 = g_xl[s * 64 + 32 + lane];

    for (int p = beg; p < end; p++) {
        // prefetch next edge's source row
        int sn = (p + 1 < end) ? g_srcs[p + 1] : s;
        float nx0 = g_xl[sn * 64 + lane];
        float nx1 = g_xl[sn * 64 + 32 + lane];

        float e0 = x0 + xr0; e0 = e0 > 0.f ? e0 : 0.2f * e0;
        float e1 = x1 + xr1; e1 = e1 > 0.f ? e1 : 0.2f * e1;
        float part = e0 * att0 + e1 * att1;
        #pragma unroll
        for (int off = 16; off >= 1; off >>= 1)
            part += __shfl_xor_sync(0xffffffffu, part, off);
        // part == logit, replicated on all lanes (warp-uniform)

        if (part <= m) {                 // common path: 1 MUFU
            float a = __expf(part - m);
            denom += a; acc0 += a * x0; acc1 += a * x1;
        } else {                          // new max: rescale (a == 1)
            float sc = __expf(m - part);
            denom = denom * sc + 1.0f;
            acc0  = acc0  * sc + x0;
            acc1  = acc1  * sc + x1;
            m = part;
        }
        x0 = nx0; x1 = nx1;
    }

    float inv = 1.0f / (denom + 1e-16f);
    float v0 = acc0 * inv + bias[lane];
    float v1 = acc1 * inv + bias[lane + 32];

    float h0 = v0 > 0.f ? v0 : (__expf(v0) - 1.0f);
    float h1 = v1 > 0.f ? v1 : (__expf(v1) - 1.0f);

    float mx = fmaxf(h0, h1);
    #pragma unroll
    for (int off = 16; off >= 1; off >>= 1)
        mx = fmaxf(mx, __shfl_xor_sync(0xffffffffu, mx, off));
    float sm = __expf(h0 - mx) + __expf(h1 - mx);
    #pragma unroll
    for (int off = 16; off >= 1; off >>= 1)
        sm += __shfl_xor_sync(0xffffffffu, sm, off);
    float lse = mx + __logf(sm);

    out[node * 64 + lane]      = h0 - lse;
    out[node * 64 + lane + 32] = h1 - lse;
}

// --------------------------------------------------------------------------
extern "C" void kernel_launch(void* const* d_in, const int* in_sizes, int n_in,
                              void* d_out, int out_size) {
    const float* x    = (const float*)d_in[0];
    const int*   ei   = (const int*)d_in[1];     // int32 (JAX x64 disabled)
    const float* Wl   = (const float*)d_in[2];
    const float* Wr   = (const float*)d_in[3];
    const float* att  = (const float*)d_in[4];
    const float* bias = (const float*)d_in[5];
    float*       out  = (float*)d_out;

    k_init<<<(NN + 511) / 512, 512>>>();
    k_count<<<(TE + 255) / 256, 256>>>(ei);
    k_gemm<<<(NN + 63) / 64, 256>>>(x, Wl, Wr);
    k_scanA<<<SCAN_G, SCAN_B>>>();
    k_scanB<<<1, 128>>>();
    k_scanC<<<SCAN_G, SCAN_B>>>();
    k_fill<<<(TE + 255) / 256, 256>>>(ei);
    k_aggr<<<NN * 32 / 256, 256>>>(out, att, bias);
}

// round 14
// speedup vs baseline: 1.1466x; 1.1466x over previous
#include <cuda_runtime.h>

#define NN   50000
#define EE   800000
#define TE   (EE + NN)
#define CIN  128
#define COUT 64

#define SCAN_B   512
#define SCAN_G   ((NN + SCAN_B - 1) / SCAN_B)   // 98

// ---- device scratch (16B-aligned for float4 access) ----
__device__ __align__(16) float g_xl[NN * COUT];     // x @ W_l
__device__ __align__(16) float g_xr[NN * COUT];     // x @ W_r
__device__ __align__(16) int   g_cnt[NN];           // per-dst degree
__device__ __align__(16) int   g_rowptr[NN + 1];    // CSR row pointers
__device__ __align__(16) int   g_cursor[NN];        // fill cursors
__device__ __align__(16) int   g_srcs[TE];          // CSR: src per slot
__device__ __align__(16) int   g_bsum[SCAN_G];      // per-block totals
__device__ __align__(16) int   g_boff[SCAN_G];      // per-block offsets

__device__ __forceinline__ int clampN(int v) {
    return v < 0 ? 0 : (v >= NN ? NN - 1 : v);
}

// ---------------------------------------------------------------- K0: init
__global__ void k_init() {
    int i = blockIdx.x * blockDim.x + threadIdx.x;
    if (i < NN) g_cnt[i] = 0;
}

// ----------------------------------------------------- K1: count edges/dst
__global__ void k_count(const int* __restrict__ ei) {
    int e = blockIdx.x * blockDim.x + threadIdx.x;
    if (e >= TE) return;
    int d = (e < EE) ? clampN(ei[EE + e]) : (e - EE);
    atomicAdd(&g_cnt[d], 1);
}

// ------------------- K2a: block-local exclusive scan + block totals
__global__ void k_scanA() {
    __shared__ int warp_sums[16];
    int tid = threadIdx.x, lane = tid & 31, wid = tid >> 5;
    int i = blockIdx.x * SCAN_B + tid;

    int v = (i < NN) ? g_cnt[i] : 0;
    int x = v;
    #pragma unroll
    for (int off = 1; off < 32; off <<= 1) {
        int y = __shfl_up_sync(0xffffffffu, x, off);
        if (lane >= off) x += y;
    }
    if (lane == 31) warp_sums[wid] = x;
    __syncthreads();
    if (wid == 0 && lane < 16) {
        int w = warp_sums[lane];
        #pragma unroll
        for (int off = 1; off < 16; off <<= 1) {
            int y = __shfl_up_sync(0x0000ffffu, w, off);
            if (lane >= off) w += y;
        }
        warp_sums[lane] = w;
    }
    __syncthreads();
    int warp_off = (wid > 0) ? warp_sums[wid - 1] : 0;
    if (i < NN) g_rowptr[i] = warp_off + x - v;
    if (tid == 0) g_bsum[blockIdx.x] = warp_sums[15];
}

// ------------------- K2b: exclusive scan of 98 block totals
__global__ void k_scanB() {
    __shared__ int s[128];
    int t = threadIdx.x;
    s[t] = (t < SCAN_G) ? g_bsum[t] : 0;
    __syncthreads();
    #pragma unroll
    for (int off = 1; off < 128; off <<= 1) {
        int v = (t >= off) ? s[t - off] : 0;
        __syncthreads();
        s[t] += v;
        __syncthreads();
    }
    if (t < SCAN_G) g_boff[t] = s[t] - g_bsum[t];
    if (t == 0) g_rowptr[NN] = TE;
}

// ------------------- K2c: apply block offsets, materialize cursors
__global__ void k_scanC() {
    int i = blockIdx.x * SCAN_B + threadIdx.x;
    if (i >= NN) return;
    int r = g_rowptr[i] + g_boff[blockIdx.x];
    g_rowptr[i] = r;
    g_cursor[i] = r;
}

// ------------------------------------------- K3: x@[W_l|W_r] fused GEMM
// Scalar FFMA version (measured best): 64 rows/block, 256 threads,
// static 48KB smem, K chunked in halves of 64.
__global__ void k_gemm(const float* __restrict__ x,
                       const float* __restrict__ Wl,
                       const float* __restrict__ Wr) {
    __shared__ float Ws[64 * 128];   // 32KB
    __shared__ float xs[64 * 64];    // 16KB

    const int tid  = threadIdx.x;
    const int base = blockIdx.x * 64;
    const int tx = tid & 31, ty = tid >> 5;

    float acc[8][4];
    #pragma unroll
    for (int i = 0; i < 8; i++)
        #pragma unroll
        for (int j = 0; j < 4; j++) acc[i][j] = 0.0f;

    for (int kc = 0; kc < 2; kc++) {
        const int k0 = kc * 64;
        for (int idx = tid * 4; idx < 64 * 128; idx += 256 * 4) {
            int k = k0 + (idx >> 7), c = idx & 127;
            const float* p = (c < 64) ? (Wl + k * 64 + c)
                                      : (Wr + k * 64 + (c - 64));
            *(float4*)&Ws[idx] = *(const float4*)p;
        }
        for (int idx = tid * 4; idx < 64 * 64; idx += 256 * 4) {
            int r = idx >> 6;
            int row = base + r;
            float4 v = make_float4(0.f, 0.f, 0.f, 0.f);
            if (row < NN) v = *(const float4*)&x[row * CIN + k0 + (idx & 63)];
            *(float4*)&xs[idx] = v;
        }
        __syncthreads();

        #pragma unroll 4
        for (int k = 0; k < 64; k++) {
            float wv[4];
            #pragma unroll
            for (int j = 0; j < 4; j++) wv[j] = Ws[k * 128 + tx + 32 * j];
            #pragma unroll
            for (int i = 0; i < 8; i++) {
                float xv = xs[(ty + 8 * i) * 64 + k];
                #pragma unroll
                for (int j = 0; j < 4; j++) acc[i][j] += xv * wv[j];
            }
        }
        __syncthreads();
    }

    #pragma unroll
    for (int i = 0; i < 8; i++) {
        int row = base + ty + 8 * i;
        if (row >= NN) continue;
        #pragma unroll
        for (int j = 0; j < 4; j++) {
            int c = tx + 32 * j;
            if (c < 64) g_xl[row * 64 + c]        = acc[i][j];
            else        g_xr[row * 64 + (c - 64)] = acc[i][j];
        }
    }
}

// --------------------- K4: CSR src fill only (no math)
__global__ void k_fill(const int* __restrict__ ei) {
    int e = blockIdx.x * blockDim.x + threadIdx.x;
    if (e >= TE) return;
    int s, d;
    if (e < EE) { s = clampN(ei[e]); d = clampN(ei[EE + e]); }
    else        { s = d = e - EE; }
    int pos = atomicAdd(&g_cursor[d], 1);
    g_srcs[pos] = s;
}

// -------- K5: fused online-softmax aggregation (2 edges/iter, branchless)
// Measured best aggr variant.
__global__ void k_aggr(float* __restrict__ out,
                       const float* __restrict__ att,
                       const float* __restrict__ bias) {
    int node = (blockIdx.x * blockDim.x + threadIdx.x) >> 5;
    int lane = threadIdx.x & 31;

    int beg = g_rowptr[node], end = g_rowptr[node + 1];

    float att0 = att[lane],  att1 = att[lane + 32];
    float xr0  = g_xr[node * 64 + lane];
    float xr1  = g_xr[node * 64 + 32 + lane];

    float m = -3.4e38f, denom = 0.f, acc0 = 0.f, acc1 = 0.f;

    int p = beg;
    for (; p + 1 < end; p += 2) {
        int s0 = g_srcs[p], s1 = g_srcs[p + 1];
        float a00 = g_xl[s0 * 64 + lane];
        float a01 = g_xl[s0 * 64 + 32 + lane];
        float b00 = g_xl[s1 * 64 + lane];
        float b01 = g_xl[s1 * 64 + 32 + lane];

        float e0 = a00 + xr0; e0 = e0 > 0.f ? e0 : 0.2f * e0;
        float e1 = a01 + xr1; e1 = e1 > 0.f ? e1 : 0.2f * e1;
        float f0 = b00 + xr0; f0 = f0 > 0.f ? f0 : 0.2f * f0;
        float f1 = b01 + xr1; f1 = f1 > 0.f ? f1 : 0.2f * f1;
        float pa = e0 * att0 + e1 * att1;
        float pb = f0 * att0 + f1 * att1;
        #pragma unroll
        for (int off = 16; off >= 1; off >>= 1) {
            pa += __shfl_xor_sync(0xffffffffu, pa, off);
            pb += __shfl_xor_sync(0xffffffffu, pb, off);
        }

        float mnew = fmaxf(m, fmaxf(pa, pb));
        float sc = __expf(m - mnew);
        float wa = __expf(pa - mnew);
        float wb = __expf(pb - mnew);
        denom = denom * sc + wa + wb;
        acc0  = acc0  * sc + wa * a00 + wb * b00;
        acc1  = acc1  * sc + wa * a01 + wb * b01;
        m = mnew;
    }
    if (p < end) {
        int s0 = g_srcs[p];
        float a00 = g_xl[s0 * 64 + lane];
        float a01 = g_xl[s0 * 64 + 32 + lane];
        float e0 = a00 + xr0; e0 = e0 > 0.f ? e0 : 0.2f * e0;
        float e1 = a01 + xr1; e1 = e1 > 0.f ? e1 : 0.2f * e1;
        float pa = e0 * att0 + e1 * att1;
        #pragma unroll
        for (int off = 16; off >= 1; off >>= 1)
            pa += __shfl_xor_sync(0xffffffffu, pa, off);
        float mnew = fmaxf(m, pa);
        float sc = __expf(m - mnew);
        float wa = __expf(pa - mnew);
        denom = denom * sc + wa;
        acc0  = acc0  * sc + wa * a00;
        acc1  = acc1  * sc + wa * a01;
        m = mnew;
    }

    float inv = 1.0f / (denom + 1e-16f);
    float v0 = acc0 * inv + bias[lane];
    float v1 = acc1 * inv + bias[lane + 32];

    float h0 = v0 > 0.f ? v0 : (__expf(v0) - 1.0f);
    float h1 = v1 > 0.f ? v1 : (__expf(v1) - 1.0f);

    float mx = fmaxf(h0, h1);
    #pragma unroll
    for (int off = 16; off >= 1; off >>= 1)
        mx = fmaxf(mx, __shfl_xor_sync(0xffffffffu, mx, off));
    float sm = __expf(h0 - mx) + __expf(h1 - mx);
    #pragma unroll
    for (int off = 16; off >= 1; off >>= 1)
        sm += __shfl_xor_sync(0xffffffffu, sm, off);
    float lse = mx + __logf(sm);

    out[node * 64 + lane]      = h0 - lse;
    out[node * 64 + lane + 32] = h1 - lse;
}

// --------------------------------------------------------------------------
extern "C" void kernel_launch(void* const* d_in, const int* in_sizes, int n_in,
                              void* d_out, int out_size) {
    const float* x    = (const float*)d_in[0];
    const int*   ei   = (const int*)d_in[1];     // int32 (JAX x64 disabled)
    const float* Wl   = (const float*)d_in[2];
    const float* Wr   = (const float*)d_in[3];
    const float* att  = (const float*)d_in[4];
    const float* bias = (const float*)d_in[5];
    float*       out  = (float*)d_out;

    k_init<<<(NN + 511) / 512, 512>>>();
    k_count<<<(TE + 255) / 256, 256>>>(ei);
    k_gemm<<<(NN + 63) / 64, 256>>>(x, Wl, Wr);
    k_scanA<<<SCAN_G, SCAN_B>>>();
    k_scanB<<<1, 128>>>();
    k_scanC<<<SCAN_G, SCAN_B>>>();
    k_fill<<<(TE + 255) / 256, 256>>>(ei);
    k_aggr<<<NN * 32 / 256, 256>>>(out, att, bias);
}

// round 15
// speedup vs baseline: 1.2709x; 1.1084x over previous
#include <cuda_runtime.h>

#define NN   50000
#define EE   800000
#define TE   (EE + NN)
#define CIN  128
#define COUT 64

#define SCAN_B   512
#define SCAN_G   ((NN + SCAN_B - 1) / SCAN_B)   // 98

// ---- device scratch (16B-aligned for float4 access) ----
__device__ __align__(16) float g_xl[NN * COUT];     // x @ W_l
__device__ __align__(16) float g_xr[NN * COUT];     // x @ W_r
__device__ __align__(16) int   g_cnt[NN];           // per-dst degree
__device__ __align__(16) int   g_rowptr[NN + 1];    // CSR row pointers
__device__ __align__(16) int   g_cursor[NN];        // fill cursors
__device__ __align__(16) int   g_srcs[TE];          // CSR: src per slot
__device__ __align__(16) int   g_bsum[SCAN_G];      // per-block totals
__device__ __align__(16) int   g_boff[SCAN_G];      // per-block offsets

__device__ __forceinline__ int clampN(int v) {
    return v < 0 ? 0 : (v >= NN ? NN - 1 : v);
}

// ---------------------------------------------------------------- K0: init
__global__ void k_init() {
    int i = blockIdx.x * blockDim.x + threadIdx.x;
    if (i < NN) g_cnt[i] = 0;
}

// ----------------------------------------------------- K1: count edges/dst
__global__ void k_count(const int* __restrict__ ei) {
    int e = blockIdx.x * blockDim.x + threadIdx.x;
    if (e >= TE) return;
    int d = (e < EE) ? clampN(ei[EE + e]) : (e - EE);
    atomicAdd(&g_cnt[d], 1);
}

// ------------------- K2a: block-local exclusive scan + block totals
__global__ void k_scanA() {
    __shared__ int warp_sums[16];
    int tid = threadIdx.x, lane = tid & 31, wid = tid >> 5;
    int i = blockIdx.x * SCAN_B + tid;

    int v = (i < NN) ? g_cnt[i] : 0;
    int x = v;
    #pragma unroll
    for (int off = 1; off < 32; off <<= 1) {
        int y = __shfl_up_sync(0xffffffffu, x, off);
        if (lane >= off) x += y;
    }
    if (lane == 31) warp_sums[wid] = x;
    __syncthreads();
    if (wid == 0 && lane < 16) {
        int w = warp_sums[lane];
        #pragma unroll
        for (int off = 1; off < 16; off <<= 1) {
            int y = __shfl_up_sync(0x0000ffffu, w, off);
            if (lane >= off) w += y;
        }
        warp_sums[lane] = w;
    }
    __syncthreads();
    int warp_off = (wid > 0) ? warp_sums[wid - 1] : 0;
    if (i < NN) g_rowptr[i] = warp_off + x - v;
    if (tid == 0) g_bsum[blockIdx.x] = warp_sums[15];
}

// ------------------- K2b: exclusive scan of 98 block totals
__global__ void k_scanB() {
    __shared__ int s[128];
    int t = threadIdx.x;
    s[t] = (t < SCAN_G) ? g_bsum[t] : 0;
    __syncthreads();
    #pragma unroll
    for (int off = 1; off < 128; off <<= 1) {
        int v = (t >= off) ? s[t - off] : 0;
        __syncthreads();
        s[t] += v;
        __syncthreads();
    }
    if (t < SCAN_G) g_boff[t] = s[t] - g_bsum[t];
    if (t == 0) g_rowptr[NN] = TE;
}

// ------------------- K2c: apply block offsets, materialize cursors
__global__ void k_scanC() {
    int i = blockIdx.x * SCAN_B + threadIdx.x;
    if (i >= NN) return;
    int r = g_rowptr[i] + g_boff[blockIdx.x];
    g_rowptr[i] = r;
    g_cursor[i] = r;
}

// ------------------------------------------- K3: x@[W_l|W_r] fused GEMM
// Scalar FFMA version (measured best): 64 rows/block, 256 threads,
// static 48KB smem, K chunked in halves of 64.
__global__ void k_gemm(const float* __restrict__ x,
                       const float* __restrict__ Wl,
                       const float* __restrict__ Wr) {
    __shared__ float Ws[64 * 128];   // 32KB
    __shared__ float xs[64 * 64];    // 16KB

    const int tid  = threadIdx.x;
    const int base = blockIdx.x * 64;
    const int tx = tid & 31, ty = tid >> 5;

    float acc[8][4];
    #pragma unroll
    for (int i = 0; i < 8; i++)
        #pragma unroll
        for (int j = 0; j < 4; j++) acc[i][j] = 0.0f;

    for (int kc = 0; kc < 2; kc++) {
        const int k0 = kc * 64;
        for (int idx = tid * 4; idx < 64 * 128; idx += 256 * 4) {
            int k = k0 + (idx >> 7), c = idx & 127;
            const float* p = (c < 64) ? (Wl + k * 64 + c)
                                      : (Wr + k * 64 + (c - 64));
            *(float4*)&Ws[idx] = *(const float4*)p;
        }
        for (int idx = tid * 4; idx < 64 * 64; idx += 256 * 4) {
            int r = idx >> 6;
            int row = base + r;
            float4 v = make_float4(0.f, 0.f, 0.f, 0.f);
            if (row < NN) v = *(const float4*)&x[row * CIN + k0 + (idx & 63)];
            *(float4*)&xs[idx] = v;
        }
        __syncthreads();

        #pragma unroll 4
        for (int k = 0; k < 64; k++) {
            float wv[4];
            #pragma unroll
            for (int j = 0; j < 4; j++) wv[j] = Ws[k * 128 + tx + 32 * j];
            #pragma unroll
            for (int i = 0; i < 8; i++) {
                float xv = xs[(ty + 8 * i) * 64 + k];
                #pragma unroll
                for (int j = 0; j < 4; j++) acc[i][j] += xv * wv[j];
            }
        }
        __syncthreads();
    }

    #pragma unroll
    for (int i = 0; i < 8; i++) {
        int row = base + ty + 8 * i;
        if (row >= NN) continue;
        #pragma unroll
        for (int j = 0; j < 4; j++) {
            int c = tx + 32 * j;
            if (c < 64) g_xl[row * 64 + c]        = acc[i][j];
            else        g_xr[row * 64 + (c - 64)] = acc[i][j];
        }
    }
}

// --------------------- K4: CSR src fill only (no math)
__global__ void k_fill(const int* __restrict__ ei) {
    int e = blockIdx.x * blockDim.x + threadIdx.x;
    if (e >= TE) return;
    int s, d;
    if (e < EE) { s = clampN(ei[e]); d = clampN(ei[EE + e]); }
    else        { s = d = e - EE; }
    int pos = atomicAdd(&g_cursor[d], 1);
    g_srcs[pos] = s;
}

// -------- K5: fused online-softmax aggregation (2 edges/iter, branchless)
__global__ void k_aggr(float* __restrict__ out,
                       const float* __restrict__ att,
                       const float* __restrict__ bias) {
    int node = (blockIdx.x * blockDim.x + threadIdx.x) >> 5;
    int lane = threadIdx.x & 31;

    int beg = g_rowptr[node], end = g_rowptr[node + 1];

    float att0 = att[lane],  att1 = att[lane + 32];
    float xr0  = g_xr[node * 64 + lane];
    float xr1  = g_xr[node * 64 + 32 + lane];

    float m = -3.4e38f, denom = 0.f, acc0 = 0.f, acc1 = 0.f;

    int p = beg;
    for (; p + 1 < end; p += 2) {
        int s0 = g_srcs[p], s1 = g_srcs[p + 1];
        float a00 = g_xl[s0 * 64 + lane];
        float a01 = g_xl[s0 * 64 + 32 + lane];
        float b00 = g_xl[s1 * 64 + lane];
        float b01 = g_xl[s1 * 64 + 32 + lane];

        float e0 = a00 + xr0; e0 = e0 > 0.f ? e0 : 0.2f * e0;
        float e1 = a01 + xr1; e1 = e1 > 0.f ? e1 : 0.2f * e1;
        float f0 = b00 + xr0; f0 = f0 > 0.f ? f0 : 0.2f * f0;
        float f1 = b01 + xr1; f1 = f1 > 0.f ? f1 : 0.2f * f1;
        float pa = e0 * att0 + e1 * att1;
        float pb = f0 * att0 + f1 * att1;
        #pragma unroll
        for (int off = 16; off >= 1; off >>= 1) {
            pa += __shfl_xor_sync(0xffffffffu, pa, off);
            pb += __shfl_xor_sync(0xffffffffu, pb, off);
        }

        float mnew = fmaxf(m, fmaxf(pa, pb));
        float sc = __expf(m - mnew);
        float wa = __expf(pa - mnew);
        float wb = __expf(pb - mnew);
        denom = denom * sc + wa + wb;
        acc0  = acc0  * sc + wa * a00 + wb * b00;
        acc1  = acc1  * sc + wa * a01 + wb * b01;
        m = mnew;
    }
    if (p < end) {
        int s0 = g_srcs[p];
        float a00 = g_xl[s0 * 64 + lane];
        float a01 = g_xl[s0 * 64 + 32 + lane];
        float e0 = a00 + xr0; e0 = e0 > 0.f ? e0 : 0.2f * e0;
        float e1 = a01 + xr1; e1 = e1 > 0.f ? e1 : 0.2f * e1;
        float pa = e0 * att0 + e1 * att1;
        #pragma unroll
        for (int off = 16; off >= 1; off >>= 1)
            pa += __shfl_xor_sync(0xffffffffu, pa, off);
        float mnew = fmaxf(m, pa);
        float sc = __expf(m - mnew);
        float wa = __expf(pa - mnew);
        denom = denom * sc + wa;
        acc0  = acc0  * sc + wa * a00;
        acc1  = acc1  * sc + wa * a01;
        m = mnew;
    }

    float inv = 1.0f / (denom + 1e-16f);
    float v0 = acc0 * inv + bias[lane];
    float v1 = acc1 * inv + bias[lane + 32];

    float h0 = v0 > 0.f ? v0 : (__expf(v0) - 1.0f);
    float h1 = v1 > 0.f ? v1 : (__expf(v1) - 1.0f);

    float mx = fmaxf(h0, h1);
    #pragma unroll
    for (int off = 16; off >= 1; off >>= 1)
        mx = fmaxf(mx, __shfl_xor_sync(0xffffffffu, mx, off));
    float sm = __expf(h0 - mx) + __expf(h1 - mx);
    #pragma unroll
    for (int off = 16; off >= 1; off >>= 1)
        sm += __shfl_xor_sync(0xffffffffu, sm, off);
    float lse = mx + __logf(sm);

    out[node * 64 + lane]      = h0 - lse;
    out[node * 64 + lane + 32] = h1 - lse;
}

// --------------------------------------------------------------------------
// Fork-join: CSR branch (count->scan->fill) runs concurrently with k_gemm on
// a second stream; k_aggr joins both. Streams/events created once (host-side
// objects only; first call is the uncaptured correctness run).
extern "C" void kernel_launch(void* const* d_in, const int* in_sizes, int n_in,
                              void* d_out, int out_size) {
    const float* x    = (const float*)d_in[0];
    const int*   ei   = (const int*)d_in[1];     // int32 (JAX x64 disabled)
    const float* Wl   = (const float*)d_in[2];
    const float* Wr   = (const float*)d_in[3];
    const float* att  = (const float*)d_in[4];
    const float* bias = (const float*)d_in[5];
    float*       out  = (float*)d_out;

    static cudaStream_t s_csr = nullptr;
    static cudaEvent_t  ev_fork = nullptr, ev_join = nullptr;
    if (s_csr == nullptr) {
        cudaStreamCreateWithFlags(&s_csr, cudaStreamNonBlocking);
        cudaEventCreateWithFlags(&ev_fork, cudaEventDisableTiming);
        cudaEventCreateWithFlags(&ev_join, cudaEventDisableTiming);
    }

    // origin stream: init, then fork
    k_init<<<(NN + 511) / 512, 512>>>();
    cudaEventRecord(ev_fork, 0);

    // CSR branch on side stream
    cudaStreamWaitEvent(s_csr, ev_fork, 0);
    k_count<<<(TE + 255) / 256, 256, 0, s_csr>>>(ei);
    k_scanA<<<SCAN_G, SCAN_B, 0, s_csr>>>();
    k_scanB<<<1, 128, 0, s_csr>>>();
    k_scanC<<<SCAN_G, SCAN_B, 0, s_csr>>>();
    k_fill<<<(TE + 255) / 256, 256, 0, s_csr>>>(ei);
    cudaEventRecord(ev_join, s_csr);

    // GEMM branch on origin stream (overlaps CSR build)
    k_gemm<<<(NN + 63) / 64, 256>>>(x, Wl, Wr);

    // join, then aggregate
    cudaStreamWaitEvent(0, ev_join, 0);
    k_aggr<<<NN * 32 / 256, 256>>>(out, att, bias);
}